// round 5
// baseline (speedup 1.0000x reference)
#include <cuda_runtime.h>
#include <cuda_bf16.h>

// Problem constants (fixed shapes per reference)
#define Nn   100000
#define Ee   1600000
#define FIN  128
#define FHID 32
#define FOUT 2

// ---------------- scratch (__device__ globals; no allocation) ----------------
__device__ __align__(16) float g_g1[Nn * FHID];   // dinv-scaled h1    12.8 MB
__device__ __align__(8)  float g_g2[Nn * FOUT];   // dinv-scaled h2     0.8 MB
__device__ int g_cnt[Nn];                          // in-degree (no self loop)
__device__ int g_ptr[Nn + 1];                      // CSR row pointers (by target)
__device__ int g_cur[Nn];                          // fill cursors
__device__ int g_adj[Ee];                          // CSR: source node per slot

// ---------------- kernels ----------------

// zero histogram
__global__ void k_zero() {
    int t = blockIdx.x * blockDim.x + threadIdx.x;
    if (t < Nn) g_cnt[t] = 0;
}

// in-degree histogram (edge_index int32: [0:E]=row/src, [E:2E]=col/dst)
__global__ void k_hist(const int* __restrict__ ei) {
    int e = blockIdx.x * blockDim.x + threadIdx.x;
    if (e >= Ee) return;
    atomicAdd(&g_cnt[ei[Ee + e]], 1);   // RED.ADD (return unused)
}

// single-block exclusive scan over g_cnt -> g_ptr, g_cur
__global__ void __launch_bounds__(1024) k_scan() {
    __shared__ int warpsum[32];
    int t = threadIdx.x;
    const int CH = (Nn + 1023) / 1024;          // 98
    int start = t * CH;
    int end = start + CH; if (end > Nn) end = Nn;
    int s = 0;
    for (int i = start; i < end; i++) s += g_cnt[i];
    int lane = t & 31, wid = t >> 5;
    int v = s;
#pragma unroll
    for (int o = 1; o < 32; o <<= 1) {
        int u = __shfl_up_sync(0xffffffffu, v, o);
        if (lane >= o) v += u;
    }
    if (lane == 31) warpsum[wid] = v;
    __syncthreads();
    if (wid == 0) {
        int w = warpsum[lane];
#pragma unroll
        for (int o = 1; o < 32; o <<= 1) {
            int u = __shfl_up_sync(0xffffffffu, w, o);
            if (lane >= o) w += u;
        }
        warpsum[lane] = w;
    }
    __syncthreads();
    int off = v - s + (wid ? warpsum[wid - 1] : 0);  // exclusive prefix
    int run = off;
    for (int i = start; i < end; i++) {
        g_ptr[i] = run; g_cur[i] = run; run += g_cnt[i];
    }
    if (t == 1023) g_ptr[Nn] = run;    // = Ee
}

// CSR fill: append source r to target c's list
__global__ void k_fill(const int* __restrict__ ei) {
    int e = blockIdx.x * blockDim.x + threadIdx.x;
    if (e >= Ee) return;
    int r = ei[e];
    int c = ei[Ee + e];
    int pos = atomicAdd(&g_cur[c], 1);
    g_adj[pos] = r;
}

// g1 = dinv * (x @ W1) — 4 nodes/thread register blocking, 32 nodes/block
__global__ void __launch_bounds__(256) k_gemm1(const float* __restrict__ x,
                                               const float* __restrict__ W1) {
    __shared__ float sW[FIN * FHID];   // 16 KB
    __shared__ float sx[32 * FIN];     // 16 KB
    int tid = threadIdx.x;
    for (int i = tid; i < FIN * FHID; i += 256) sW[i] = W1[i];

    int nodeBase = blockIdx.x * 32;    // Nn % 32 == 0 -> no bounds checks
    {   // coalesced float4 load of 32 x-rows (1024 float4s, 4 per thread)
        const float4* x4 = reinterpret_cast<const float4*>(x);
        float4* sx4 = reinterpret_cast<float4*>(sx);
#pragma unroll
        for (int i = tid; i < 1024; i += 256) {
            int node = nodeBase + (i >> 5);
            sx4[i] = x4[(size_t)node * 32 + (i & 31)];
        }
    }
    __syncthreads();

    int w = tid >> 5, lane = tid & 31;
    int n0 = w * 4;                    // local node base for this warp
    const float4* sx4 = reinterpret_cast<const float4*>(sx);
    float acc0 = 0.f, acc1 = 0.f, acc2 = 0.f, acc3 = 0.f;
#pragma unroll
    for (int k4 = 0; k4 < 32; k4++) {
        float4 a = sx4[(n0 + 0) * 32 + k4];
        float4 b = sx4[(n0 + 1) * 32 + k4];
        float4 c = sx4[(n0 + 2) * 32 + k4];
        float4 d = sx4[(n0 + 3) * 32 + k4];
        float xa[4] = {a.x, a.y, a.z, a.w};
        float xb[4] = {b.x, b.y, b.z, b.w};
        float xc[4] = {c.x, c.y, c.z, c.w};
        float xd[4] = {d.x, d.y, d.z, d.w};
#pragma unroll
        for (int q = 0; q < 4; q++) {
            float wv = sW[(k4 * 4 + q) * FHID + lane];
            acc0 = fmaf(xa[q], wv, acc0);
            acc1 = fmaf(xb[q], wv, acc1);
            acc2 = fmaf(xc[q], wv, acc2);
            acc3 = fmaf(xd[q], wv, acc3);
        }
    }
    int gn = nodeBase + n0;
    float d0 = rsqrtf((float)g_cnt[gn + 0] + 1.0f);
    float d1 = rsqrtf((float)g_cnt[gn + 1] + 1.0f);
    float d2 = rsqrtf((float)g_cnt[gn + 2] + 1.0f);
    float d3 = rsqrtf((float)g_cnt[gn + 3] + 1.0f);
    g_g1[(gn + 0) * FHID + lane] = d0 * acc0;
    g_g1[(gn + 1) * FHID + lane] = d1 * acc1;
    g_g1[(gn + 2) * FHID + lane] = d2 * acc2;
    g_g1[(gn + 3) * FHID + lane] = d3 * acc3;
}

// layer-1 gather-aggregate fused with layer-2 transform:
// agg = sum_{r in N(n)} g1[r] + g1[n];  a = relu(dinv*agg + b1);  g2 = dinv*(a@W2)
// warp per node: lane = esub*8 + j; esub handles every 4th edge, j = float4 feature chunk
__global__ void __launch_bounds__(256) k_g1agg(const float* __restrict__ b1,
                                               const float* __restrict__ W2) {
    int n    = (blockIdx.x * blockDim.x + threadIdx.x) >> 5;   // grid sized exactly
    int lane = threadIdx.x & 31;
    int j    = lane & 7;
    int esub = lane >> 3;
    int p0 = g_ptr[n], p1 = g_ptr[n + 1];
    const float4* g1f4 = reinterpret_cast<const float4*>(g_g1);

    float4 acc = make_float4(0.f, 0.f, 0.f, 0.f);
    for (int k = p0 + esub; k < p1; k += 4) {
        int r = g_adj[k];                       // broadcast within 8-lane subgroup
        float4 v = g1f4[r * 8 + j];             // 128B line per subgroup
        acc.x += v.x; acc.y += v.y; acc.z += v.z; acc.w += v.w;
    }
    // reduce across the 4 edge-subgroups (lanes differing in bits 3,4)
#pragma unroll
    for (int m = 8; m <= 16; m <<= 1) {
        acc.x += __shfl_xor_sync(0xffffffffu, acc.x, m);
        acc.y += __shfl_xor_sync(0xffffffffu, acc.y, m);
        acc.z += __shfl_xor_sync(0xffffffffu, acc.z, m);
        acc.w += __shfl_xor_sync(0xffffffffu, acc.w, m);
    }
    // self loop
    float4 sv = g1f4[n * 8 + j];
    acc.x += sv.x; acc.y += sv.y; acc.z += sv.z; acc.w += sv.w;

    float dinv = rsqrtf((float)(p1 - p0) + 1.0f);
    float4 bb = reinterpret_cast<const float4*>(b1)[j];
    float a0 = fmaxf(fmaf(dinv, acc.x, bb.x), 0.f);
    float a1 = fmaxf(fmaf(dinv, acc.y, bb.y), 0.f);
    float a2 = fmaxf(fmaf(dinv, acc.z, bb.z), 0.f);
    float a3 = fmaxf(fmaf(dinv, acc.w, bb.w), 0.f);

    // W2 rows for features 4j..4j+3 : floats [8j .. 8j+7]
    float4 w0 = reinterpret_cast<const float4*>(W2)[j * 2 + 0]; // f4j:{c0,c1} f4j+1:{c0,c1}
    float4 w1 = reinterpret_cast<const float4*>(W2)[j * 2 + 1]; // f4j+2, f4j+3
    float pp0 = a0 * w0.x + a1 * w0.z + a2 * w1.x + a3 * w1.z;
    float pp1 = a0 * w0.y + a1 * w0.w + a2 * w1.y + a3 * w1.w;
    // reduce across j (bits 0..2); values replicated across esub so stay in-group
#pragma unroll
    for (int m = 1; m <= 4; m <<= 1) {
        pp0 += __shfl_xor_sync(0xffffffffu, pp0, m);
        pp1 += __shfl_xor_sync(0xffffffffu, pp1, m);
    }
    if (lane == 0) {
        reinterpret_cast<float2*>(g_g2)[n] = make_float2(dinv * pp0, dinv * pp1);
    }
}

// layer-2 gather + bias + log_softmax, warp per node
__global__ void __launch_bounds__(256) k_g2final(const float* __restrict__ b2,
                                                 float* __restrict__ out) {
    int n    = (blockIdx.x * blockDim.x + threadIdx.x) >> 5;
    int lane = threadIdx.x & 31;
    int p0 = g_ptr[n], p1 = g_ptr[n + 1];
    const float2* g2f2 = reinterpret_cast<const float2*>(g_g2);
    float s0 = 0.f, s1 = 0.f;
    for (int k = p0 + lane; k < p1; k += 32) {
        float2 v = g2f2[g_adj[k]];
        s0 += v.x; s1 += v.y;
    }
#pragma unroll
    for (int m = 16; m > 0; m >>= 1) {
        s0 += __shfl_xor_sync(0xffffffffu, s0, m);
        s1 += __shfl_xor_sync(0xffffffffu, s1, m);
    }
    if (lane == 0) {
        float2 sv = g2f2[n];
        float dinv = rsqrtf((float)(p1 - p0) + 1.0f);
        float o0 = dinv * (s0 + sv.x) + b2[0];
        float o1 = dinv * (s1 + sv.y) + b2[1];
        float mx = fmaxf(o0, o1);
        float lse = mx + logf(expf(o0 - mx) + expf(o1 - mx));
        reinterpret_cast<float2*>(out)[n] = make_float2(o0 - lse, o1 - lse);
    }
}

// ---------------- launch ----------------
extern "C" void kernel_launch(void* const* d_in, const int* in_sizes, int n_in,
                              void* d_out, int out_size) {
    const float* x  = (const float*)d_in[0];
    const int*   ei = (const int*)d_in[1];   // int32 on the wire
    const float* W1 = (const float*)d_in[2];
    const float* b1 = (const float*)d_in[3];
    const float* W2 = (const float*)d_in[4];
    const float* b2 = (const float*)d_in[5];
    float* out = (float*)d_out;

    const int T = 256;
    k_zero   <<<(Nn + T - 1) / T, T>>>();
    k_hist   <<<(Ee + T - 1) / T, T>>>(ei);
    k_scan   <<<1, 1024>>>();
    k_fill   <<<(Ee + T - 1) / T, T>>>(ei);
    k_gemm1  <<<Nn / 32, T>>>(x, W1);               // 100000 % 32 == 0
    k_g1agg  <<<(Nn * 32) / T, T>>>(b1, W2);        // warp per node, exact
    k_g2final<<<(Nn * 32) / T, T>>>(b2, out);
}

// round 6
// speedup vs baseline: 2.1821x; 2.1821x over previous
#include <cuda_runtime.h>
#include <cuda_bf16.h>

// Problem constants (fixed shapes per reference)
#define Nn   100000
#define Ee   1600000
#define FIN  128
#define FHID 32
#define FOUT 2

// ---------------- scratch (__device__ globals; no allocation) ----------------
__device__ __align__(16) float g_g1[Nn * FHID];     // dinv-scaled h1        12.8 MB
__device__ __align__(16) float g_agg1[Nn * FHID];   // layer-1 scatter accum 12.8 MB
__device__ __align__(8)  float g_g2[Nn * FOUT];     // dinv-scaled h2         0.8 MB
__device__ __align__(8)  float g_agg2[Nn * FOUT];   // layer-2 scatter accum  0.8 MB
__device__ int g_cnt[Nn];                            // in-degree (no self loop)

// ---------------- kernels ----------------

// zero degree histogram + agg2
__global__ void k_zero() {
    int t = blockIdx.x * blockDim.x + threadIdx.x;
    if (t < Nn) {
        g_cnt[t] = 0;
        reinterpret_cast<float2*>(g_agg2)[t] = make_float2(0.f, 0.f);
    }
}

// degree histogram (int RED) + zero agg1 (reuses the same big grid)
__global__ void k_prep(const int* __restrict__ ei) {
    int e = blockIdx.x * blockDim.x + threadIdx.x;
    if (e < Nn * (FHID / 4)) {  // 800K float4s
        reinterpret_cast<float4*>(g_agg1)[e] = make_float4(0.f, 0.f, 0.f, 0.f);
    }
    if (e < Ee) {
        atomicAdd(&g_cnt[ei[Ee + e]], 1);   // RED.ADD (return unused)
    }
}

// g1 = dinv * (x @ W1) — 4 nodes/thread register blocking, 32 nodes/block
__global__ void __launch_bounds__(256) k_gemm1(const float* __restrict__ x,
                                               const float* __restrict__ W1) {
    __shared__ float sW[FIN * FHID];   // 16 KB
    __shared__ float sx[32 * FIN];     // 16 KB
    int tid = threadIdx.x;
    for (int i = tid; i < FIN * FHID; i += 256) sW[i] = W1[i];

    int nodeBase = blockIdx.x * 32;    // Nn % 32 == 0 -> no bounds checks
    {   // coalesced float4 load of 32 x-rows (1024 float4s, 4 per thread)
        const float4* x4 = reinterpret_cast<const float4*>(x);
        float4* sx4 = reinterpret_cast<float4*>(sx);
#pragma unroll
        for (int i = tid; i < 1024; i += 256) {
            int node = nodeBase + (i >> 5);
            sx4[i] = x4[(size_t)node * 32 + (i & 31)];
        }
    }
    __syncthreads();

    int w = tid >> 5, lane = tid & 31;
    int n0 = w * 4;                    // local node base for this warp
    const float4* sx4 = reinterpret_cast<const float4*>(sx);
    float acc0 = 0.f, acc1 = 0.f, acc2 = 0.f, acc3 = 0.f;
#pragma unroll
    for (int k4 = 0; k4 < 32; k4++) {
        float4 a = sx4[(n0 + 0) * 32 + k4];
        float4 b = sx4[(n0 + 1) * 32 + k4];
        float4 c = sx4[(n0 + 2) * 32 + k4];
        float4 d = sx4[(n0 + 3) * 32 + k4];
        float xa[4] = {a.x, a.y, a.z, a.w};
        float xb[4] = {b.x, b.y, b.z, b.w};
        float xc[4] = {c.x, c.y, c.z, c.w};
        float xd[4] = {d.x, d.y, d.z, d.w};
#pragma unroll
        for (int q = 0; q < 4; q++) {
            float wv = sW[(k4 * 4 + q) * FHID + lane];
            acc0 = fmaf(xa[q], wv, acc0);
            acc1 = fmaf(xb[q], wv, acc1);
            acc2 = fmaf(xc[q], wv, acc2);
            acc3 = fmaf(xd[q], wv, acc3);
        }
    }
    int gn = nodeBase + n0;
    float d0 = rsqrtf((float)g_cnt[gn + 0] + 1.0f);
    float d1 = rsqrtf((float)g_cnt[gn + 1] + 1.0f);
    float d2 = rsqrtf((float)g_cnt[gn + 2] + 1.0f);
    float d3 = rsqrtf((float)g_cnt[gn + 3] + 1.0f);
    g_g1[(gn + 0) * FHID + lane] = d0 * acc0;
    g_g1[(gn + 1) * FHID + lane] = d1 * acc1;
    g_g1[(gn + 2) * FHID + lane] = d2 * acc2;
    g_g1[(gn + 3) * FHID + lane] = d3 * acc3;
}

// layer-1 edge scatter: 8 lanes per edge, float4 gather + vector RED
__global__ void k_scatter1(const int* __restrict__ ei) {
    unsigned int t = blockIdx.x * blockDim.x + threadIdx.x;
    if (t >= (unsigned int)Ee * 8u) return;
    int e = t >> 3;
    int j = t & 7;
    int r = ei[e];
    int c = ei[Ee + e];
    float4 v = reinterpret_cast<const float4*>(g_g1)[r * (FHID / 4) + j];
    float4* dst = reinterpret_cast<float4*>(g_agg1) + c * (FHID / 4) + j;
    atomicAdd(dst, v);                 // RED.E.ADD.F32x4 (return unused)
}

// a1 = relu(dinv*(agg1 + g1) + b1); h2 = a1 @ W2; g2 = dinv * h2
__global__ void __launch_bounds__(256) k_layer2(const float* __restrict__ b1,
                                                const float* __restrict__ W2) {
    int w    = (blockIdx.x * blockDim.x + threadIdx.x) >> 5;
    int lane = threadIdx.x & 31;
    if (w >= Nn) return;
    float dinv = rsqrtf((float)g_cnt[w] + 1.0f);
    float a = dinv * (g_agg1[w * FHID + lane] + g_g1[w * FHID + lane]) + b1[lane];
    a = fmaxf(a, 0.f);
    float p0 = a * W2[lane * 2 + 0];
    float p1 = a * W2[lane * 2 + 1];
#pragma unroll
    for (int o = 16; o > 0; o >>= 1) {
        p0 += __shfl_xor_sync(0xffffffffu, p0, o);
        p1 += __shfl_xor_sync(0xffffffffu, p1, o);
    }
    if (lane == 0) {
        reinterpret_cast<float2*>(g_g2)[w] = make_float2(dinv * p0, dinv * p1);
    }
}

// layer-2 edge scatter: 1 thread per edge, float2 gather + vector RED
__global__ void k_scatter2(const int* __restrict__ ei) {
    int e = blockIdx.x * blockDim.x + threadIdx.x;
    if (e >= Ee) return;
    int r = ei[e];
    int c = ei[Ee + e];
    float2 v = reinterpret_cast<const float2*>(g_g2)[r];
    float2* dst = reinterpret_cast<float2*>(g_agg2) + c;
    atomicAdd(dst, v);                 // RED.E.ADD.F32x2
}

// finalize: o = dinv*(agg2 + g2) + b2; log_softmax over 2 classes
__global__ void k_final(const float* __restrict__ b2, float* __restrict__ out) {
    int n = blockIdx.x * blockDim.x + threadIdx.x;
    if (n >= Nn) return;
    float dinv = rsqrtf((float)g_cnt[n] + 1.0f);
    float2 s = reinterpret_cast<const float2*>(g_agg2)[n];
    float2 g = reinterpret_cast<const float2*>(g_g2)[n];
    float o0 = dinv * (s.x + g.x) + b2[0];
    float o1 = dinv * (s.y + g.y) + b2[1];
    float m = fmaxf(o0, o1);
    float lse = m + logf(expf(o0 - m) + expf(o1 - m));
    reinterpret_cast<float2*>(out)[n] = make_float2(o0 - lse, o1 - lse);
}

// ---------------- launch ----------------
extern "C" void kernel_launch(void* const* d_in, const int* in_sizes, int n_in,
                              void* d_out, int out_size) {
    const float* x  = (const float*)d_in[0];
    const int*   ei = (const int*)d_in[1];   // int32 on the wire
    const float* W1 = (const float*)d_in[2];
    const float* b1 = (const float*)d_in[3];
    const float* W2 = (const float*)d_in[4];
    const float* b2 = (const float*)d_in[5];
    float* out = (float*)d_out;

    const int T = 256;
    k_zero    <<<(Nn + T - 1) / T, T>>>();
    k_prep    <<<(Ee + T - 1) / T, T>>>(ei);
    k_gemm1   <<<Nn / 32, T>>>(x, W1);            // 100000 % 32 == 0
    k_scatter1<<<((unsigned)Ee * 8u + T - 1) / T, T>>>(ei);
    k_layer2  <<<(Nn * 32 + T - 1) / T, T>>>(b1, W2);
    k_scatter2<<<(Ee + T - 1) / T, T>>>(ei);
    k_final   <<<(Nn + T - 1) / T, T>>>(b2, out);
}

// round 7
// speedup vs baseline: 2.2779x; 1.0439x over previous
#include <cuda_runtime.h>
#include <cuda_fp16.h>
#include <cuda_bf16.h>

// Problem constants (fixed shapes per reference)
#define Nn   100000
#define Ee   1600000
#define FIN  128
#define FHID 32
#define FOUT 2

// ---------------- scratch (__device__ globals; no allocation) ----------------
__device__ __align__(16) __half g_g1h[Nn * FHID];   // dinv-scaled h1 (fp16)   6.4 MB
__device__ __align__(16) __half g_agg1h[Nn * FHID]; // layer-1 accum (fp16)    6.4 MB
__device__ __align__(8)  float g_g2[Nn * FOUT];     // dinv-scaled h2          0.8 MB
__device__ __align__(8)  float g_agg2[Nn * FOUT];   // layer-2 accum           0.8 MB
__device__ int g_cnt[Nn];                            // in-degree (no self loop)

// ---------------- kernels ----------------

// zero degree histogram
__global__ void k_zero() {
    int t = blockIdx.x * blockDim.x + threadIdx.x;
    if (t < Nn) g_cnt[t] = 0;
}

// degree histogram (edge_index int32: [0:E]=src, [E:2E]=dst)
__global__ void k_hist(const int* __restrict__ ei) {
    int e = blockIdx.x * blockDim.x + threadIdx.x;
    if (e >= Ee) return;
    atomicAdd(&g_cnt[ei[Ee + e]], 1);   // RED.ADD (return unused)
}

// g1 = dinv * (x @ W1), stored fp16; agg1 initialized with self-loop term (= g1)
// 4 nodes/thread register blocking, 32 nodes/block
__global__ void __launch_bounds__(256) k_gemm1(const float* __restrict__ x,
                                               const float* __restrict__ W1) {
    __shared__ float sW[FIN * FHID];   // 16 KB
    __shared__ float sx[32 * FIN];     // 16 KB
    int tid = threadIdx.x;
    for (int i = tid; i < FIN * FHID; i += 256) sW[i] = W1[i];

    int nodeBase = blockIdx.x * 32;    // Nn % 32 == 0 -> no bounds checks
    {   // coalesced float4 load of 32 x-rows (1024 float4s, 4 per thread)
        const float4* x4 = reinterpret_cast<const float4*>(x);
        float4* sx4 = reinterpret_cast<float4*>(sx);
#pragma unroll
        for (int i = tid; i < 1024; i += 256) {
            int node = nodeBase + (i >> 5);
            sx4[i] = x4[(size_t)node * 32 + (i & 31)];
        }
    }
    __syncthreads();

    int w = tid >> 5, lane = tid & 31;
    int n0 = w * 4;                    // local node base for this warp
    const float4* sx4 = reinterpret_cast<const float4*>(sx);
    float acc0 = 0.f, acc1 = 0.f, acc2 = 0.f, acc3 = 0.f;
#pragma unroll
    for (int k4 = 0; k4 < 32; k4++) {
        float4 a = sx4[(n0 + 0) * 32 + k4];
        float4 b = sx4[(n0 + 1) * 32 + k4];
        float4 c = sx4[(n0 + 2) * 32 + k4];
        float4 d = sx4[(n0 + 3) * 32 + k4];
        float xa[4] = {a.x, a.y, a.z, a.w};
        float xb[4] = {b.x, b.y, b.z, b.w};
        float xc[4] = {c.x, c.y, c.z, c.w};
        float xd[4] = {d.x, d.y, d.z, d.w};
#pragma unroll
        for (int q = 0; q < 4; q++) {
            float wv = sW[(k4 * 4 + q) * FHID + lane];
            acc0 = fmaf(xa[q], wv, acc0);
            acc1 = fmaf(xb[q], wv, acc1);
            acc2 = fmaf(xc[q], wv, acc2);
            acc3 = fmaf(xd[q], wv, acc3);
        }
    }
    int gn = nodeBase + n0;
    float d0 = rsqrtf((float)g_cnt[gn + 0] + 1.0f);
    float d1 = rsqrtf((float)g_cnt[gn + 1] + 1.0f);
    float d2 = rsqrtf((float)g_cnt[gn + 2] + 1.0f);
    float d3 = rsqrtf((float)g_cnt[gn + 3] + 1.0f);
    __half h0 = __float2half_rn(d0 * acc0);
    __half h1 = __float2half_rn(d1 * acc1);
    __half h2 = __float2half_rn(d2 * acc2);
    __half h3 = __float2half_rn(d3 * acc3);
    g_g1h  [(gn + 0) * FHID + lane] = h0;
    g_g1h  [(gn + 1) * FHID + lane] = h1;
    g_g1h  [(gn + 2) * FHID + lane] = h2;
    g_g1h  [(gn + 3) * FHID + lane] = h3;
    g_agg1h[(gn + 0) * FHID + lane] = h0;   // self-loop init
    g_agg1h[(gn + 1) * FHID + lane] = h1;
    g_agg1h[(gn + 2) * FHID + lane] = h2;
    g_agg1h[(gn + 3) * FHID + lane] = h3;
}

// layer-1 edge scatter (fp16): 4 lanes per edge, 16B gather + v4.f16x2 RED
__global__ void k_scatter1(const int* __restrict__ ei) {
    unsigned int t = blockIdx.x * blockDim.x + threadIdx.x;
    if (t >= (unsigned int)Ee * 4u) return;
    int e = t >> 2;
    int j = t & 3;
    int r = ei[e];
    int c = ei[Ee + e];
    uint4 v = reinterpret_cast<const uint4*>(g_g1h)[r * 4 + j];   // 8 halves
    __half* dst = g_agg1h + c * FHID + j * 8;
    asm volatile("red.global.add.noftz.v4.f16x2 [%0], {%1,%2,%3,%4};"
                 :: "l"(dst), "r"(v.x), "r"(v.y), "r"(v.z), "r"(v.w) : "memory");
}

// a1 = relu(dinv*agg1 + b1); g2 = dinv*(a1 @ W2); agg2 init = g2 (self loop)
__global__ void __launch_bounds__(256) k_layer2(const float* __restrict__ b1,
                                                const float* __restrict__ W2) {
    int w    = (blockIdx.x * blockDim.x + threadIdx.x) >> 5;
    int lane = threadIdx.x & 31;
    if (w >= Nn) return;
    float dinv = rsqrtf((float)g_cnt[w] + 1.0f);
    float a = dinv * __half2float(g_agg1h[w * FHID + lane]) + b1[lane];
    a = fmaxf(a, 0.f);
    float p0 = a * W2[lane * 2 + 0];
    float p1 = a * W2[lane * 2 + 1];
#pragma unroll
    for (int o = 16; o > 0; o >>= 1) {
        p0 += __shfl_xor_sync(0xffffffffu, p0, o);
        p1 += __shfl_xor_sync(0xffffffffu, p1, o);
    }
    if (lane == 0) {
        float2 g = make_float2(dinv * p0, dinv * p1);
        reinterpret_cast<float2*>(g_g2)[w]   = g;
        reinterpret_cast<float2*>(g_agg2)[w] = g;   // self-loop init
    }
}

// layer-2 edge scatter: 1 thread per edge, float2 gather + vector RED (fp32)
__global__ void k_scatter2(const int* __restrict__ ei) {
    int e = blockIdx.x * blockDim.x + threadIdx.x;
    if (e >= Ee) return;
    int r = ei[e];
    int c = ei[Ee + e];
    float2 v = reinterpret_cast<const float2*>(g_g2)[r];
    float2* dst = reinterpret_cast<float2*>(g_agg2) + c;
    atomicAdd(dst, v);                 // RED.E.ADD.F32x2
}

// finalize: o = dinv*agg2 + b2; log_softmax over 2 classes
__global__ void k_final(const float* __restrict__ b2, float* __restrict__ out) {
    int n = blockIdx.x * blockDim.x + threadIdx.x;
    if (n >= Nn) return;
    float dinv = rsqrtf((float)g_cnt[n] + 1.0f);
    float2 s = reinterpret_cast<const float2*>(g_agg2)[n];
    float o0 = dinv * s.x + b2[0];
    float o1 = dinv * s.y + b2[1];
    float m = fmaxf(o0, o1);
    float lse = m + logf(expf(o0 - m) + expf(o1 - m));
    reinterpret_cast<float2*>(out)[n] = make_float2(o0 - lse, o1 - lse);
}

// ---------------- launch ----------------
extern "C" void kernel_launch(void* const* d_in, const int* in_sizes, int n_in,
                              void* d_out, int out_size) {
    const float* x  = (const float*)d_in[0];
    const int*   ei = (const int*)d_in[1];   // int32 on the wire
    const float* W1 = (const float*)d_in[2];
    const float* b1 = (const float*)d_in[3];
    const float* W2 = (const float*)d_in[4];
    const float* b2 = (const float*)d_in[5];
    float* out = (float*)d_out;

    const int T = 256;
    k_zero    <<<(Nn + T - 1) / T, T>>>();
    k_hist    <<<(Ee + T - 1) / T, T>>>(ei);
    k_gemm1   <<<Nn / 32, T>>>(x, W1);                    // 100000 % 32 == 0
    k_scatter1<<<((unsigned)Ee * 4u) / T, T>>>(ei);       // exact: 6.4M/256
    k_layer2  <<<(Nn * 32 + T - 1) / T, T>>>(b1, W2);
    k_scatter2<<<(Ee + T - 1) / T, T>>>(ei);
    k_final   <<<(Nn + T - 1) / T, T>>>(b2, out);
}

// round 9
// speedup vs baseline: 2.5389x; 1.1146x over previous
#include <cuda_runtime.h>
#include <cuda_fp16.h>
#include <cuda_bf16.h>

// Problem constants (fixed shapes per reference)
#define Nn   100000
#define Ee   1600000
#define FIN  128
#define FHID 32
#define FOUT 2

// ---------------- scratch (__device__ globals; no allocation) ----------------
__device__ __align__(16) __half g_g1h[Nn * FHID];   // dinv-scaled h1 (fp16)   6.4 MB
__device__ __align__(16) __half g_agg1h[Nn * FHID]; // layer-1 accum (fp16)    6.4 MB
__device__ __align__(8)  float g_g2[Nn * FOUT];     // dinv-scaled h2          0.8 MB
__device__ __align__(8)  float g_agg2[Nn * FOUT];   // layer-2 accum           0.8 MB
__device__ int g_cnt[Nn];                            // in-degree (no self loop)

// ---------------- kernels ----------------

// zero degree histogram
__global__ void k_zero() {
    int t = blockIdx.x * blockDim.x + threadIdx.x;
    if (t < Nn) g_cnt[t] = 0;
}

// degree histogram, int4-vectorized (4 edges/thread)
__global__ void k_hist(const int* __restrict__ ei) {
    int t = blockIdx.x * blockDim.x + threadIdx.x;
    if (t >= Ee / 4) return;
    int4 c = reinterpret_cast<const int4*>(ei + Ee)[t];
    atomicAdd(&g_cnt[c.x], 1);
    atomicAdd(&g_cnt[c.y], 1);
    atomicAdd(&g_cnt[c.z], 1);
    atomicAdd(&g_cnt[c.w], 1);
}

// g1 = dinv * (x @ W1) via packed fma.rn.f32x2; 8 nodes/warp, 64 nodes/block.
// Stores fp16 g1 and initializes agg1 with the self-loop term.
__global__ void __launch_bounds__(256) k_gemm1(const float* __restrict__ x,
                                               const float* __restrict__ W1) {
    __shared__ __align__(16) float sWp[FIN * FHID]; // paired: u64[p*32+lane]={W[2p],W[2p+1]}  16 KB
    __shared__ __align__(16) float sx[64 * FIN];    // 64 x-rows                               32 KB
    int tid = threadIdx.x;
    for (int i = tid; i < FIN * FHID; i += 256) {
        int k = i >> 5, lane = i & 31;
        sWp[(((k >> 1) * 32) + lane) * 2 + (k & 1)] = W1[i];
    }
    int nodeBase = blockIdx.x * 64;
    {
        const float4* x4 = reinterpret_cast<const float4*>(x);
        float4* sx4 = reinterpret_cast<float4*>(sx);
        for (int i = tid; i < 2048; i += 256) {
            int node = nodeBase + (i >> 5);
            sx4[i] = (node < Nn) ? x4[(size_t)node * 32 + (i & 31)]
                                 : make_float4(0.f, 0.f, 0.f, 0.f);
        }
    }
    __syncthreads();

    int w = tid >> 5, lane = tid & 31;
    int n0 = w * 8;                                   // local node base
    const ulonglong2* sxq = reinterpret_cast<const ulonglong2*>(sx);      // 32 per 128-float row
    const unsigned long long* sWq = reinterpret_cast<const unsigned long long*>(sWp);

    unsigned long long acc[8];
#pragma unroll
    for (int i = 0; i < 8; i++) acc[i] = 0ULL;        // {0.f, 0.f}

#pragma unroll
    for (int kp2 = 0; kp2 < 32; kp2++) {              // covers k = 4*kp2 .. 4*kp2+3
        unsigned long long w0 = sWq[(2 * kp2 + 0) * 32 + lane];
        unsigned long long w1 = sWq[(2 * kp2 + 1) * 32 + lane];
#pragma unroll
        for (int i = 0; i < 8; i++) {
            ulonglong2 xv = sxq[(n0 + i) * 32 + kp2]; // FIXED: row stride = 32 ulonglong2
            asm("fma.rn.f32x2 %0, %1, %2, %0;" : "+l"(acc[i]) : "l"(xv.x), "l"(w0));
            asm("fma.rn.f32x2 %0, %1, %2, %0;" : "+l"(acc[i]) : "l"(xv.y), "l"(w1));
        }
    }

#pragma unroll
    for (int i = 0; i < 8; i++) {
        int gn = nodeBase + n0 + i;
        if (gn < Nn) {
            float lo, hi;
            asm("mov.b64 {%0,%1}, %2;" : "=f"(lo), "=f"(hi) : "l"(acc[i]));
            float dinv = rsqrtf((float)g_cnt[gn] + 1.0f);
            __half h = __float2half_rn(dinv * (lo + hi));
            g_g1h  [gn * FHID + lane] = h;
            g_agg1h[gn * FHID + lane] = h;            // self-loop init
        }
    }
}

// layer-1 edge scatter (fp16): 4 lanes per edge, 16B gather + v4.f16x2 RED
__global__ void k_scatter1(const int* __restrict__ ei) {
    unsigned int t = blockIdx.x * blockDim.x + threadIdx.x;
    if (t >= (unsigned int)Ee * 4u) return;
    int e = t >> 2;
    int j = t & 3;
    int r = ei[e];
    int c = ei[Ee + e];
    uint4 v = reinterpret_cast<const uint4*>(g_g1h)[r * 4 + j];   // 8 halves
    __half* dst = g_agg1h + c * FHID + j * 8;
    asm volatile("red.global.add.noftz.v4.f16x2 [%0], {%1,%2,%3,%4};"
                 :: "l"(dst), "r"(v.x), "r"(v.y), "r"(v.z), "r"(v.w) : "memory");
}

// a1 = relu(dinv*agg1 + b1); g2 = dinv*(a1 @ W2); agg2 init = g2 (self loop)
__global__ void __launch_bounds__(256) k_layer2(const float* __restrict__ b1,
                                                const float* __restrict__ W2) {
    int w    = (blockIdx.x * blockDim.x + threadIdx.x) >> 5;
    int lane = threadIdx.x & 31;
    if (w >= Nn) return;
    float dinv = rsqrtf((float)g_cnt[w] + 1.0f);
    float a = dinv * __half2float(g_agg1h[w * FHID + lane]) + b1[lane];
    a = fmaxf(a, 0.f);
    float p0 = a * W2[lane * 2 + 0];
    float p1 = a * W2[lane * 2 + 1];
#pragma unroll
    for (int o = 16; o > 0; o >>= 1) {
        p0 += __shfl_xor_sync(0xffffffffu, p0, o);
        p1 += __shfl_xor_sync(0xffffffffu, p1, o);
    }
    if (lane == 0) {
        float2 g = make_float2(dinv * p0, dinv * p1);
        reinterpret_cast<float2*>(g_g2)[w]   = g;
        reinterpret_cast<float2*>(g_agg2)[w] = g;   // self-loop init
    }
}

// layer-2 edge scatter: 2 edges/thread, float2 gathers + vector RED (fp32)
__global__ void k_scatter2(const int* __restrict__ ei) {
    int t = blockIdx.x * blockDim.x + threadIdx.x;
    if (t >= Ee / 2) return;
    int2 r = reinterpret_cast<const int2*>(ei)[t];
    int2 c = reinterpret_cast<const int2*>(ei + Ee)[t];
    float2 v0 = reinterpret_cast<const float2*>(g_g2)[r.x];
    float2 v1 = reinterpret_cast<const float2*>(g_g2)[r.y];
    atomicAdd(reinterpret_cast<float2*>(g_agg2) + c.x, v0);
    atomicAdd(reinterpret_cast<float2*>(g_agg2) + c.y, v1);
}

// finalize: o = dinv*agg2 + b2; log_softmax over 2 classes
__global__ void k_final(const float* __restrict__ b2, float* __restrict__ out) {
    int n = blockIdx.x * blockDim.x + threadIdx.x;
    if (n >= Nn) return;
    float dinv = rsqrtf((float)g_cnt[n] + 1.0f);
    float2 s = reinterpret_cast<const float2*>(g_agg2)[n];
    float o0 = dinv * s.x + b2[0];
    float o1 = dinv * s.y + b2[1];
    float m = fmaxf(o0, o1);
    float lse = m + logf(expf(o0 - m) + expf(o1 - m));
    reinterpret_cast<float2*>(out)[n] = make_float2(o0 - lse, o1 - lse);
}

// ---------------- launch ----------------
extern "C" void kernel_launch(void* const* d_in, const int* in_sizes, int n_in,
                              void* d_out, int out_size) {
    const float* x  = (const float*)d_in[0];
    const int*   ei = (const int*)d_in[1];   // int32 on the wire
    const float* W1 = (const float*)d_in[2];
    const float* b1 = (const float*)d_in[3];
    const float* W2 = (const float*)d_in[4];
    const float* b2 = (const float*)d_in[5];
    float* out = (float*)d_out;

    const int T = 256;
    k_zero    <<<(Nn + T - 1) / T, T>>>();
    k_hist    <<<(Ee / 4 + T - 1) / T, T>>>(ei);
    k_gemm1   <<<(Nn + 63) / 64, T>>>(x, W1);
    k_scatter1<<<((unsigned)Ee * 4u) / T, T>>>(ei);       // exact: 6.4M/256
    k_layer2  <<<(Nn * 32 + T - 1) / T, T>>>(b1, W2);
    k_scatter2<<<(Ee / 2 + T - 1) / T, T>>>(ei);
    k_final   <<<(Nn + T - 1) / T, T>>>(b2, out);
}

// round 10
// speedup vs baseline: 2.7371x; 1.0781x over previous
#include <cuda_runtime.h>
#include <cuda_fp16.h>
#include <cuda_bf16.h>

// Problem constants (fixed shapes per reference)
#define Nn   100000
#define Ee   1600000
#define FIN  128
#define FHID 32
#define FOUT 2

// ---------------- scratch (__device__ globals; no allocation) ----------------
// NOTE: g_cnt relies on CUDA's zero-initialization of __device__ globals at
// module load; k_final restores it to zero at the end of every call.
__device__ __align__(16) __half g_g1h[Nn * FHID];   // dinv-scaled h1 (fp16)   6.4 MB
__device__ __align__(16) __half g_agg1h[Nn * FHID]; // layer-1 accum (fp16)    6.4 MB
__device__ __align__(8)  float g_g2[Nn * FOUT];     // dinv-scaled h2          0.8 MB
__device__ __align__(8)  float g_agg2[Nn * FOUT];   // layer-2 accum           0.8 MB
__device__ int g_cnt[Nn];                            // in-degree (no self loop)

// ---------------- kernels ----------------

// degree histogram, int4-vectorized (4 edges/thread)
__global__ void k_hist(const int* __restrict__ ei) {
    int t = blockIdx.x * blockDim.x + threadIdx.x;
    if (t >= Ee / 4) return;
    int4 c = reinterpret_cast<const int4*>(ei + Ee)[t];
    atomicAdd(&g_cnt[c.x], 1);
    atomicAdd(&g_cnt[c.y], 1);
    atomicAdd(&g_cnt[c.z], 1);
    atomicAdd(&g_cnt[c.w], 1);
}

// g1 = dinv * (x @ W1) via packed fma.rn.f32x2; 8 nodes/warp, 64 nodes/block.
// Stores fp16 g1 and initializes agg1 with the self-loop term.
__global__ void __launch_bounds__(256) k_gemm1(const float* __restrict__ x,
                                               const float* __restrict__ W1) {
    __shared__ __align__(16) float sWp[FIN * FHID]; // paired: u64[p*32+lane]={W[2p],W[2p+1]}  16 KB
    __shared__ __align__(16) float sx[64 * FIN];    // 64 x-rows                               32 KB
    int tid = threadIdx.x;
    for (int i = tid; i < FIN * FHID; i += 256) {
        int k = i >> 5, lane = i & 31;
        sWp[(((k >> 1) * 32) + lane) * 2 + (k & 1)] = W1[i];
    }
    int nodeBase = blockIdx.x * 64;
    {
        const float4* x4 = reinterpret_cast<const float4*>(x);
        float4* sx4 = reinterpret_cast<float4*>(sx);
        for (int i = tid; i < 2048; i += 256) {
            int node = nodeBase + (i >> 5);
            sx4[i] = (node < Nn) ? x4[(size_t)node * 32 + (i & 31)]
                                 : make_float4(0.f, 0.f, 0.f, 0.f);
        }
    }
    __syncthreads();

    int w = tid >> 5, lane = tid & 31;
    int n0 = w * 8;                                   // local node base
    const ulonglong2* sxq = reinterpret_cast<const ulonglong2*>(sx);      // 32 per 128-float row
    const unsigned long long* sWq = reinterpret_cast<const unsigned long long*>(sWp);

    unsigned long long acc[8];
#pragma unroll
    for (int i = 0; i < 8; i++) acc[i] = 0ULL;        // {0.f, 0.f}

#pragma unroll
    for (int kp2 = 0; kp2 < 32; kp2++) {              // covers k = 4*kp2 .. 4*kp2+3
        unsigned long long w0 = sWq[(2 * kp2 + 0) * 32 + lane];
        unsigned long long w1 = sWq[(2 * kp2 + 1) * 32 + lane];
#pragma unroll
        for (int i = 0; i < 8; i++) {
            ulonglong2 xv = sxq[(n0 + i) * 32 + kp2]; // row stride = 32 ulonglong2
            asm("fma.rn.f32x2 %0, %1, %2, %0;" : "+l"(acc[i]) : "l"(xv.x), "l"(w0));
            asm("fma.rn.f32x2 %0, %1, %2, %0;" : "+l"(acc[i]) : "l"(xv.y), "l"(w1));
        }
    }

#pragma unroll
    for (int i = 0; i < 8; i++) {
        int gn = nodeBase + n0 + i;
        if (gn < Nn) {
            float lo, hi;
            asm("mov.b64 {%0,%1}, %2;" : "=f"(lo), "=f"(hi) : "l"(acc[i]));
            float dinv = rsqrtf((float)g_cnt[gn] + 1.0f);
            __half h = __float2half_rn(dinv * (lo + hi));
            g_g1h  [gn * FHID + lane] = h;
            g_agg1h[gn * FHID + lane] = h;            // self-loop init
        }
    }
}

// layer-1 edge scatter (fp16): 4 lanes per edge, 16B gather + v4.f16x2 RED
__global__ void k_scatter1(const int* __restrict__ ei) {
    unsigned int t = blockIdx.x * blockDim.x + threadIdx.x;
    if (t >= (unsigned int)Ee * 4u) return;
    int e = t >> 2;
    int j = t & 3;
    int r = ei[e];
    int c = ei[Ee + e];
    uint4 v = reinterpret_cast<const uint4*>(g_g1h)[r * 4 + j];   // 8 halves
    __half* dst = g_agg1h + c * FHID + j * 8;
    asm volatile("red.global.add.noftz.v4.f16x2 [%0], {%1,%2,%3,%4};"
                 :: "l"(dst), "r"(v.x), "r"(v.y), "r"(v.z), "r"(v.w) : "memory");
}

// a1 = relu(dinv*agg1 + b1); g2 = dinv*(a1 @ W2); agg2 init = g2 (self loop)
// thread per node: 4x LDG.128 row read, 64 FMAs, W2/b1 via smem broadcast
__global__ void __launch_bounds__(256) k_layer2(const float* __restrict__ b1,
                                                const float* __restrict__ W2) {
    __shared__ float sW[FHID * FOUT];   // 64 floats
    __shared__ float sb[FHID];          // 32 floats
    int tid = threadIdx.x;
    if (tid < FHID * FOUT) sW[tid] = W2[tid];
    if (tid < FHID)        sb[tid] = b1[tid];
    __syncthreads();

    int n = blockIdx.x * 256 + tid;
    if (n >= Nn) return;
    float dinv = rsqrtf((float)g_cnt[n] + 1.0f);
    const uint4* row = reinterpret_cast<const uint4*>(g_agg1h) + n * 4;
    float p0 = 0.f, p1 = 0.f;
#pragma unroll
    for (int q = 0; q < 4; q++) {
        uint4 v = row[q];
        unsigned u[4] = {v.x, v.y, v.z, v.w};
#pragma unroll
        for (int h = 0; h < 4; h++) {
            float2 f = __half22float2(*reinterpret_cast<const __half2*>(&u[h]));
            int k = q * 8 + h * 2;
            float a0 = fmaxf(fmaf(dinv, f.x, sb[k + 0]), 0.f);
            float a1 = fmaxf(fmaf(dinv, f.y, sb[k + 1]), 0.f);
            p0 = fmaf(a0, sW[2 * k + 0], fmaf(a1, sW[2 * k + 2], p0));
            p1 = fmaf(a0, sW[2 * k + 1], fmaf(a1, sW[2 * k + 3], p1));
        }
    }
    float2 g = make_float2(dinv * p0, dinv * p1);
    reinterpret_cast<float2*>(g_g2)[n]   = g;
    reinterpret_cast<float2*>(g_agg2)[n] = g;   // self-loop init
}

// layer-2 edge scatter: 2 edges/thread, float2 gathers + vector RED (fp32)
__global__ void k_scatter2(const int* __restrict__ ei) {
    int t = blockIdx.x * blockDim.x + threadIdx.x;
    if (t >= Ee / 2) return;
    int2 r = reinterpret_cast<const int2*>(ei)[t];
    int2 c = reinterpret_cast<const int2*>(ei + Ee)[t];
    float2 v0 = reinterpret_cast<const float2*>(g_g2)[r.x];
    float2 v1 = reinterpret_cast<const float2*>(g_g2)[r.y];
    atomicAdd(reinterpret_cast<float2*>(g_agg2) + c.x, v0);
    atomicAdd(reinterpret_cast<float2*>(g_agg2) + c.y, v1);
}

// finalize: o = dinv*agg2 + b2; log_softmax; then reset g_cnt for next call
__global__ void k_final(const float* __restrict__ b2, float* __restrict__ out) {
    int n = blockIdx.x * blockDim.x + threadIdx.x;
    if (n >= Nn) return;
    float dinv = rsqrtf((float)g_cnt[n] + 1.0f);
    float2 s = reinterpret_cast<const float2*>(g_agg2)[n];
    float o0 = dinv * s.x + b2[0];
    float o1 = dinv * s.y + b2[1];
    float m = fmaxf(o0, o1);
    float lse = m + logf(expf(o0 - m) + expf(o1 - m));
    reinterpret_cast<float2*>(out)[n] = make_float2(o0 - lse, o1 - lse);
    g_cnt[n] = 0;                       // restore zero invariant for next call
}

// ---------------- launch ----------------
extern "C" void kernel_launch(void* const* d_in, const int* in_sizes, int n_in,
                              void* d_out, int out_size) {
    const float* x  = (const float*)d_in[0];
    const int*   ei = (const int*)d_in[1];   // int32 on the wire
    const float* W1 = (const float*)d_in[2];
    const float* b1 = (const float*)d_in[3];
    const float* W2 = (const float*)d_in[4];
    const float* b2 = (const float*)d_in[5];
    float* out = (float*)d_out;

    const int T = 256;
    k_hist    <<<(Ee / 4 + T - 1) / T, T>>>(ei);
    k_gemm1   <<<(Nn + 63) / 64, T>>>(x, W1);
    k_scatter1<<<((unsigned)Ee * 4u) / T, T>>>(ei);       // exact: 6.4M/256
    k_layer2  <<<(Nn + T - 1) / T, T>>>(b1, W2);
    k_scatter2<<<(Ee / 2 + T - 1) / T, T>>>(ei);
    k_final   <<<(Nn + T - 1) / T, T>>>(b2, out);
}